// round 17
// baseline (speedup 1.0000x reference)
#include <cuda_runtime.h>
#include <cuda_bf16.h>
#include <cstdint>

// AdaptiveTokenMixer: out[b,n,:] = sum_k alpha[b,n,k] * x[b,n+k,:]
// Shapes fixed: B=8, N=4096, d=256, K=8.
//
// R15 design: longest-serial-strip, single-wave, barrier-free main loop.
//  - grid 512 CTAs (64 rows each) -> ONE wave, all CTAs co-resident: no
//    wave transition, no tail.
//  - thread owns one float4 column of a 32-row strip; x via direct LDG
//    rolling ring of depth 14 (prefetch distance 7 iters ~ 300 cyc >= L2
//    hit latency). No smem round-trip for x (minimal LSU op budget).
//  - alphas for all 64 rows computed once in an overlapped prologue;
//    main loop has zero barriers: 2 LDS (alpha) + 1 LDG + 32 FFMA + 1 STG.

constexpr int K_OFF = 8;               // kernel window
constexpr int D4    = 64;              // d / 4 (float4 columns)
constexpr int RG    = 32;              // rows per thread strip
constexpr int G     = 2;               // strips per CTA
constexpr int NR    = RG * G;          // 64 rows per CTA
constexpr int RING  = 14;              // register ring depth (prefetch 6-7)
constexpr int NTHR  = 128;
constexpr int DTN   = 72;              // staged dt/mask entries (>= NR+7)

// valid_mask dtype probe (JAX bool may arrive as uint8 / int32 / float32).
// lengths >= N/2 guarantees mask[0..3] of batch 0 are all True:
//   uint8:   byte[1] == 1
//   float32: byte[1] == 0, byte[3] == 0x3f
//   int32:   byte[1] == 0, byte[3] == 0x00
__device__ __forceinline__ int probe_mask_mode(const unsigned char* vm) {
    if (vm[1] != 0) return 0;           // uint8
    if (vm[3] == 0x3f) return 2;        // float32
    return 1;                           // int32
}

__device__ __forceinline__ bool mask_at(const unsigned char* vm, int idx, int mode) {
    if (mode == 0) return vm[idx] != 0;
    if (mode == 1) return reinterpret_cast<const int*>(vm)[idx] != 0;
    return reinterpret_cast<const float*>(vm)[idx] != 0.0f;
}

__global__ __launch_bounds__(NTHR, 6) void atm_kernel(
    const float* __restrict__ x,
    const float* __restrict__ dt,
    const unsigned char* __restrict__ vm,
    const float* __restrict__ w,
    const float* __restrict__ beta,
    float* __restrict__ out,
    int N)
{
    __shared__ float4 s_alpha[NR][2];     // 8 alphas per row as two float4
    __shared__ float  s_dt[DTN];
    __shared__ int    s_vm[DTN];

    const int b   = blockIdx.y;
    const int n0  = blockIdx.x * NR;
    const int tid = threadIdx.x;

    // -------- Ring prefill (issued FIRST; overlaps the whole prologue) ------
    const int c = tid & (D4 - 1);
    const int g = tid >> 6;
    const int rbase = n0 + g * RG;

    const float4* __restrict__ xcol =
        reinterpret_cast<const float4*>(x) + (size_t)b * N * D4 + c;
    float4* __restrict__ ocol =
        reinterpret_cast<float4*>(out) + (size_t)b * N * D4 + c;

    const float4 zero4 = make_float4(0.f, 0.f, 0.f, 0.f);
    float4 win[RING];
    #pragma unroll
    for (int k = 0; k < RING; k++) {
        const int n = rbase + k;
        win[k] = (n < N) ? xcol[(size_t)n * D4] : zero4;
    }

    // -------- dt/mask parallel wavefront into smem ---------------------------
    if (tid < DTN) {
        const int mmode = probe_mask_mode(vm);
        const int n  = n0 + tid;
        const int ns = (n < N) ? n : (N - 1);
        s_dt[tid] = dt[(size_t)b * N + ns];
        s_vm[tid] = (n < N) && mask_at(vm, b * N + ns, mmode) ? 1 : 0;
    }
    __syncthreads();

    // -------- Alpha softmax for all 64 rows (smem/ALU only) ------------------
    if (tid < NR) {
        float wv[K_OFF];
        #pragma unroll
        for (int k = 0; k < K_OFF; k++) wv[k] = w[k];
        float wm = wv[0];
        #pragma unroll
        for (int k = 1; k < K_OFF; k++) wm = fmaxf(wm, wv[k]);
        float wsum = 0.f;
        #pragma unroll
        for (int k = 0; k < K_OFF; k++) { wv[k] = __expf(wv[k] - wm); wsum += wv[k]; }
        const float winv = 1.f / wsum;
        const float bsig = 1.f / (1.f + __expf(-beta[0]));

        const int   v0  = s_vm[tid];
        const float dtn = s_dt[tid];

        float sc[K_OFF];
        int   cv[K_OFF];
        #pragma unroll
        for (int k = 0; k < K_OFF; k++) {
            const int cnd = v0 & s_vm[tid + k];          // s_vm=0 beyond N
            const float td = (k == 0) ? 0.f : fmaxf(s_dt[tid + k] - dtn, 0.f);
            cv[k] = cnd;
            sc[k] = cnd ? -td : -1e9f;
        }
        float m = sc[0];
        #pragma unroll
        for (int k = 1; k < K_OFF; k++) m = fmaxf(m, sc[k]);
        float th[K_OFF];
        float es = 0.f;
        #pragma unroll
        for (int k = 0; k < K_OFF; k++) { th[k] = __expf(sc[k] - m); es += th[k]; }
        const float einv = 1.f / es;

        float a[K_OFF];
        float asum = 0.f;
        #pragma unroll
        for (int k = 0; k < K_OFF; k++) {
            const float v = bsig * (wv[k] * winv) + (1.f - bsig) * (th[k] * einv);
            a[k] = cv[k] ? v : 0.f;
            asum += a[k];
        }
        const float ainv = 1.f / fmaxf(asum, 1e-8f);
        #pragma unroll
        for (int k = 0; k < K_OFF; k++) a[k] *= ainv;
        s_alpha[tid][0] = make_float4(a[0], a[1], a[2], a[3]);
        s_alpha[tid][1] = make_float4(a[4], a[5], a[6], a[7]);
    }
    __syncthreads();    // last barrier — main loop below is barrier-free

    // -------- Main loop: 32 serial rows, rolling ring, no barriers -----------
    #pragma unroll
    for (int r = 0; r < RG; r++) {
        const int row = g * RG + r;
        const float4 a03 = s_alpha[row][0];
        const float4 a47 = s_alpha[row][1];
        const float al[K_OFF] = { a03.x, a03.y, a03.z, a03.w,
                                  a47.x, a47.y, a47.z, a47.w };

        float4 acc = zero4;
        #pragma unroll
        for (int k = 0; k < K_OFF; k++) {
            const float  a = al[k];
            const float4 v = win[(r + k) % RING];
            acc.x = fmaf(a, v.x, acc.x);
            acc.y = fmaf(a, v.y, acc.y);
            acc.z = fmaf(a, v.z, acc.z);
            acc.w = fmaf(a, v.w, acc.w);
        }
        ocol[(size_t)(rbase + r) * D4] = acc;

        // Refill slot just consumed at k=0 with row rbase+r+RING.
        // Last row needed: rbase+RG+6 -> refill while r+RING <= RG+6.
        if (r + RING <= RG + K_OFF - 2) {
            const int nl = rbase + r + RING;
            win[r % RING] = (nl < N) ? xcol[(size_t)nl * D4] : zero4;
        }
    }
}

extern "C" void kernel_launch(void* const* d_in, const int* in_sizes, int n_in,
                              void* d_out, int out_size)
{
    // metadata order: x [B,N,d] f32, delta_times [B,N] f32, valid_mask [B,N],
    //                 w [8] f32, beta [1] f32 ; output [B,N,d] f32
    const float*         x    = (const float*)d_in[0];
    const float*         dt   = (const float*)d_in[1];
    const unsigned char* vm   = (const unsigned char*)d_in[2];
    const float*         w    = (const float*)d_in[3];
    const float*         beta = (const float*)d_in[4];
    float*               out  = (float*)d_out;

    const int N = 4096;                       // fixed by problem
    const int BN = in_sizes[1];               // B*N
    const int B = BN / N;                     // 8

    dim3 grid(N / NR, B);                     // 64 x 8 = 512 CTAs: one wave
    atm_kernel<<<grid, NTHR>>>(x, dt, vm, w, beta, out, N);
}